// round 1
// baseline (speedup 1.0000x reference)
#include <cuda_runtime.h>
#include <cstdint>

#define DIN  4096
#define DOUT 4096
#define MTOT 8192
#define BM 128
#define BN 128
#define BK 32
#define NKT (DIN / BK)   // 128 k-tiles

// Fused weight scratch: W = base_T + coeff * (2*mask - 1), pre-rounded to tf32.
__device__ float g_W[(size_t)DIN * DOUT];

__device__ __forceinline__ float tf32_rna(float x) {
    uint32_t u;
    asm("cvt.rna.tf32.f32 %0, %1;" : "=r"(u) : "f"(x));
    return __uint_as_float(u);
}

__global__ void __launch_bounds__(256) fuse_kernel(const float4* __restrict__ base,
                                                   const int4* __restrict__ mask,
                                                   const float* __restrict__ coeff) {
    int i = blockIdx.x * 256 + threadIdx.x;
    float c = __ldg(coeff);
    float4 b = base[i];
    int4 m = mask[i];
    float4 w;
    w.x = tf32_rna(b.x + (m.x ? c : -c));
    w.y = tf32_rna(b.y + (m.y ? c : -c));
    w.z = tf32_rna(b.z + (m.z ? c : -c));
    w.w = tf32_rna(b.w + (m.w ? c : -c));
    reinterpret_cast<float4*>(g_W)[i] = w;
}

__device__ __forceinline__ void cp16(uint32_t dst, const void* src) {
    asm volatile("cp.async.cg.shared.global [%0], [%1], 16;\n" :: "r"(dst), "l"(src));
}

// GEMM: out[M,N] = x[M,K] @ g_W[K,N], tf32 mma.sync, double-buffered cp.async.
// Block 128x128x32, 8 warps in 4(m) x 2(n), warp tile 32x64, mma m16n8k8.
__global__ void __launch_bounds__(256) gemm_kernel(const float* __restrict__ A,
                                                   float* __restrict__ out) {
    extern __shared__ float smem[];
    float* As = smem;          // 2 stages * 128*32 floats (XOR swizzled chunks)
    float* Bs = smem + 8192;   // 2 stages * 32*128 floats (XOR swizzled chunks)

    const int tid  = threadIdx.x;
    const int lane = tid & 31;
    const int warp = tid >> 5;
    const int wm = (warp & 3) * 32;   // warp m-offset in block tile
    const int wn = (warp >> 2) * 64;  // warp n-offset
    const int r = lane >> 2;          // groupID
    const int c = lane & 3;           // threadID in group

    // Block swizzle: groups of 8 m-blocks share one n-block (L2 reuse of W column).
    int pid   = blockIdx.x;
    int local = pid & 255;            // 8 m-blocks * 32 n-blocks per group
    int g     = pid >> 8;
    int bm    = (g << 3) + (local & 7);
    int bn    = local >> 3;

    const float* Ag = A   + (size_t)bm * BM * DIN;
    const float* Wg = g_W + (size_t)bn * BN;

    uint32_t sA = (uint32_t)__cvta_generic_to_shared(As);
    uint32_t sB = (uint32_t)__cvta_generic_to_shared(Bs);

    float acc[2][8][4];
    #pragma unroll
    for (int i0 = 0; i0 < 2; i0++)
        #pragma unroll
        for (int j = 0; j < 8; j++)
            #pragma unroll
            for (int k = 0; k < 4; k++) acc[i0][j][k] = 0.f;

    auto load_stage = [&](int kt, int stage) {
        // A tile: 128 rows x 8 float4-chunks; chunk stored at (c4 ^ (m&7))
        #pragma unroll
        for (int i = 0; i < 4; i++) {
            int idx = i * 256 + tid;
            int m = idx >> 3, c4 = idx & 7;
            const float* src = Ag + (size_t)m * DIN + kt * BK + c4 * 4;
            uint32_t dst = sA + ((stage * 4096 + m * 32 + ((c4 ^ (m & 7)) << 2)) << 2);
            cp16(dst, src);
        }
        // B tile: 32 rows x 32 float4-chunks; chunk stored at (c4 ^ ((k&3)<<1))
        #pragma unroll
        for (int i = 0; i < 4; i++) {
            int idx = i * 256 + tid;
            int kk = idx >> 5, c4 = idx & 31;
            const float* src = Wg + (size_t)(kt * BK + kk) * DOUT + c4 * 4;
            uint32_t dst = sB + ((stage * 4096 + kk * 128 + ((c4 ^ ((kk & 3) << 1)) << 2)) << 2);
            cp16(dst, src);
        }
        asm volatile("cp.async.commit_group;\n");
    };

    load_stage(0, 0);

    for (int kt = 0; kt < NKT; kt++) {
        if (kt + 1 < NKT) {
            load_stage(kt + 1, (kt + 1) & 1);
            asm volatile("cp.async.wait_group 1;\n");
        } else {
            asm volatile("cp.async.wait_group 0;\n");
        }
        __syncthreads();

        const float* a_st = As + (kt & 1) * 4096;
        const float* b_st = Bs + (kt & 1) * 4096;

        #pragma unroll
        for (int ks = 0; ks < 4; ks++) {
            uint32_t afr[2][4];
            uint32_t bfr[8][2];

            #pragma unroll
            for (int mt = 0; mt < 2; mt++) {
                int m0 = wm + mt * 16 + r;
                int m1 = m0 + 8;
                int ch0 = (2 * ks) ^ r;    // (m0&7)==(m1&7)==r
                int ch1 = ch0 ^ 1;
                float v0 = a_st[m0 * 32 + (ch0 << 2) + c];
                float v1 = a_st[m1 * 32 + (ch0 << 2) + c];
                float v2 = a_st[m0 * 32 + (ch1 << 2) + c];
                float v3 = a_st[m1 * 32 + (ch1 << 2) + c];
                asm("cvt.rna.tf32.f32 %0, %1;" : "=r"(afr[mt][0]) : "f"(v0));
                asm("cvt.rna.tf32.f32 %0, %1;" : "=r"(afr[mt][1]) : "f"(v1));
                asm("cvt.rna.tf32.f32 %0, %1;" : "=r"(afr[mt][2]) : "f"(v2));
                asm("cvt.rna.tf32.f32 %0, %1;" : "=r"(afr[mt][3]) : "f"(v3));
            }
            #pragma unroll
            for (int nt = 0; nt < 8; nt++) {
                int n  = wn + nt * 8 + r;
                int k0 = ks * 8 + c;
                int k1 = k0 + 4;
                int sw = (c << 1);        // (k0&3)==(k1&3)==c
                bfr[nt][0] = __float_as_uint(b_st[k0 * 128 + (((n >> 2) ^ sw) << 2) + (n & 3)]);
                bfr[nt][1] = __float_as_uint(b_st[k1 * 128 + (((n >> 2) ^ sw) << 2) + (n & 3)]);
            }
            #pragma unroll
            for (int mt = 0; mt < 2; mt++)
                #pragma unroll
                for (int nt = 0; nt < 8; nt++) {
                    float* d = acc[mt][nt];
                    asm volatile(
                        "mma.sync.aligned.m16n8k8.row.col.f32.tf32.tf32.f32 "
                        "{%0,%1,%2,%3}, {%4,%5,%6,%7}, {%8,%9}, {%0,%1,%2,%3};\n"
                        : "+f"(d[0]), "+f"(d[1]), "+f"(d[2]), "+f"(d[3])
                        : "r"(afr[mt][0]), "r"(afr[mt][1]), "r"(afr[mt][2]), "r"(afr[mt][3]),
                          "r"(bfr[nt][0]), "r"(bfr[nt][1]));
                }
        }
        __syncthreads();
    }

    // Epilogue: c0/c1 at (r, 2c), (r, 2c+1); c2/c3 at (r+8, ...)
    #pragma unroll
    for (int mt = 0; mt < 2; mt++) {
        #pragma unroll
        for (int nt = 0; nt < 8; nt++) {
            int row = bm * BM + wm + mt * 16 + r;
            int col = bn * BN + wn + nt * 8 + c * 2;
            float2 v0 = make_float2(acc[mt][nt][0], acc[mt][nt][1]);
            float2 v1 = make_float2(acc[mt][nt][2], acc[mt][nt][3]);
            *reinterpret_cast<float2*>(out + (size_t)row * DOUT + col) = v0;
            *reinterpret_cast<float2*>(out + (size_t)(row + 8) * DOUT + col) = v1;
        }
    }
}

extern "C" void kernel_launch(void* const* d_in, const int* in_sizes, int n_in,
                              void* d_out, int out_size) {
    const float* x     = (const float*)d_in[0];
    const float* base  = (const float*)d_in[1];
    const int*   mask  = (const int*)d_in[2];
    const float* coeff = (const float*)d_in[3];
    float* out = (float*)d_out;

    // 1) Fuse weights: W = tf32(base + coeff * sign(mask))
    fuse_kernel<<<(DIN * (size_t)DOUT / 4) / 256, 256>>>(
        (const float4*)base, (const int4*)mask, coeff);

    // 2) GEMM: out = x @ W  (tf32 mma, fp32 accumulate)
    cudaFuncSetAttribute(gemm_kernel, cudaFuncAttributeMaxDynamicSharedMemorySize, 65536);
    gemm_kernel<<<(MTOT / BM) * (DOUT / BN), 256, 65536>>>(x, out);
}

// round 4
// speedup vs baseline: 1.5270x; 1.5270x over previous
#include <cuda_runtime.h>
#include <cuda_fp16.h>
#include <cstdint>

#define DIN   4096
#define DOUT  4096
#define MTOT  8192
#define BM    128
#define BN    128
#define BK    32
#define NKT   (DIN / BK)      // 128
#define STAGES 4
#define ASTAGE 10240          // 128 rows * 5 chunks * 16B (padded)
#define STAGEB 20480          // A + B per stage

// Packed fp16 operand tiles. Tile (mb,kt) / (nb,kt) = 4096 halves contiguous,
// chunk c (16B, 8 halves) = row (c>>2), kchunk (c&3). A: [M][K]; B: [N][K] (W transposed).
__device__ __half g_A[(size_t)MTOT * DIN];
__device__ __half g_B[(size_t)DOUT * DIN];

__device__ __forceinline__ uint32_t smem_u32(const void* p) {
    uint32_t a;
    asm("{ .reg .u64 t; cvta.to.shared.u64 t, %1; cvt.u32.u64 %0, t; }" : "=r"(a) : "l"(p));
    return a;
}
__device__ __forceinline__ void cp16(uint32_t dst, const void* src) {
    asm volatile("cp.async.cg.shared.global [%0], [%1], 16;\n" :: "r"(dst), "l"(src));
}

// ---------- pack x -> fp16 tiles ----------
__global__ void __launch_bounds__(256) pack_x(const float* __restrict__ x) {
    int mb = blockIdx.x, kt = blockIdx.y;
    __half* tile = g_A + ((size_t)(mb * NKT + kt) << 12);
    #pragma unroll
    for (int it = 0; it < 2; it++) {
        int cid = it * 256 + threadIdx.x;            // 512 chunks of 8 halves
        int row = cid >> 2, kc = cid & 3;
        const float4* src = (const float4*)(x + (size_t)(mb * 128 + row) * DIN + kt * BK + kc * 8);
        float4 f0 = src[0], f1 = src[1];
        __half2 h0 = __floats2half2_rn(f0.x, f0.y);
        __half2 h1 = __floats2half2_rn(f0.z, f0.w);
        __half2 h2 = __floats2half2_rn(f1.x, f1.y);
        __half2 h3 = __floats2half2_rn(f1.z, f1.w);
        uint4 v;
        v.x = *(uint32_t*)&h0; v.y = *(uint32_t*)&h1;
        v.z = *(uint32_t*)&h2; v.w = *(uint32_t*)&h3;
        *(uint4*)(tile + cid * 8) = v;
    }
}

// ---------- fuse W = base + c*sign, transpose to [N][K] fp16 tiles ----------
__global__ void __launch_bounds__(256) pack_w(const float* __restrict__ base,
                                              const int* __restrict__ mask,
                                              const float* __restrict__ coeff) {
    __shared__ uint32_t sw32[128 * 17];              // [n][kpair], pad 17
    int nb = blockIdx.x, kt = blockIdx.y;
    int t = threadIdx.x;
    float c = __ldg(coeff);
    int n = t & 127, hsel = t >> 7;
    #pragma unroll
    for (int i = 0; i < 8; i++) {
        int kp = hsel * 8 + i;
        size_t off0 = (size_t)(kt * BK + kp * 2) * DOUT + nb * 128 + n;
        size_t off1 = off0 + DOUT;
        float w0 = base[off0] + (mask[off0] ? c : -c);
        float w1 = base[off1] + (mask[off1] ? c : -c);
        __half2 h = __floats2half2_rn(w0, w1);
        sw32[n * 17 + kp] = *(uint32_t*)&h;
    }
    __syncthreads();
    __half* tile = g_B + ((size_t)(nb * NKT + kt) << 12);
    #pragma unroll
    for (int it = 0; it < 2; it++) {
        int cid = it * 256 + t;
        int nn = cid >> 2, kc = cid & 3;
        uint4 v;
        v.x = sw32[nn * 17 + kc * 4 + 0];
        v.y = sw32[nn * 17 + kc * 4 + 1];
        v.z = sw32[nn * 17 + kc * 4 + 2];
        v.w = sw32[nn * 17 + kc * 4 + 3];
        *(uint4*)(tile + cid * 8) = v;
    }
}

// ---------- fp16 GEMM: out = A @ B^T, mma.m16n8k16, fp32 accumulate ----------
__global__ void __launch_bounds__(256, 2) gemm_fp16(float* __restrict__ out) {
    extern __shared__ char smem[];
    const uint32_t sbase = smem_u32(smem);

    const int tid  = threadIdx.x;
    const int lane = tid & 31;
    const int warp = tid >> 5;
    const int wm = (warp & 1) * 64;    // warp tile 64(m) x 32(n)
    const int wn = (warp >> 1) * 32;

    // L2 block swizzle: 8 m-blocks share one n-block column
    int pid = blockIdx.x;
    int local = pid & 255, g = pid >> 8;
    int bm = (g << 3) + (local & 7);
    int bn = local >> 3;

    const __half* tA0 = g_A + ((size_t)bm * NKT << 12);
    const __half* tB0 = g_B + ((size_t)bn * NKT << 12);

    // ldmatrix per-lane base offsets (padded stride-5-chunk layout)
    const int j = lane >> 3, sub = lane & 7;
    uint32_t aoff[4], boff[2];
    #pragma unroll
    for (int mt = 0; mt < 4; mt++) {
        int m = wm + mt * 16 + (j & 1) * 8 + sub;
        aoff[mt] = (uint32_t)((m * 5 + (j >> 1)) << 4);
    }
    #pragma unroll
    for (int np = 0; np < 2; np++) {
        int n = wn + np * 16 + (j >> 1) * 8 + sub;
        boff[np] = (uint32_t)((n * 5 + (j & 1)) << 4) + ASTAGE;
    }

    float acc[4][4][4];
    #pragma unroll
    for (int a = 0; a < 4; a++)
        #pragma unroll
        for (int b = 0; b < 4; b++)
            #pragma unroll
            for (int d = 0; d < 4; d++) acc[a][b][d] = 0.f;

    auto issue = [&](int kt, int stage) {
        const __half* tA = tA0 + ((size_t)kt << 12);
        const __half* tB = tB0 + ((size_t)kt << 12);
        #pragma unroll
        for (int it = 0; it < 2; it++) {
            int cid = it * 256 + tid;
            uint32_t d = sbase + stage * STAGEB + ((((cid >> 2) * 5) + (cid & 3)) << 4);
            cp16(d, tA + cid * 8);
            cp16(d + ASTAGE, tB + cid * 8);
        }
        asm volatile("cp.async.commit_group;\n");
    };

    issue(0, 0); issue(1, 1); issue(2, 2);

    #pragma unroll 1
    for (int kt = 0; kt < NKT; kt++) {
        if (kt + 3 < NKT) issue(kt + 3, (kt + 3) & 3);
        else asm volatile("cp.async.commit_group;\n");
        asm volatile("cp.async.wait_group 3;\n");
        __syncthreads();

        const uint32_t st = sbase + (kt & 3) * STAGEB;
        #pragma unroll
        for (int ks = 0; ks < 2; ks++) {
            uint32_t a[4][4], b[2][4];
            #pragma unroll
            for (int mt = 0; mt < 4; mt++)
                asm volatile("ldmatrix.sync.aligned.m8n8.x4.shared.b16 {%0,%1,%2,%3}, [%4];"
                             : "=r"(a[mt][0]), "=r"(a[mt][1]), "=r"(a[mt][2]), "=r"(a[mt][3])
                             : "r"(st + aoff[mt] + ks * 32));
            #pragma unroll
            for (int np = 0; np < 2; np++)
                asm volatile("ldmatrix.sync.aligned.m8n8.x4.shared.b16 {%0,%1,%2,%3}, [%4];"
                             : "=r"(b[np][0]), "=r"(b[np][1]), "=r"(b[np][2]), "=r"(b[np][3])
                             : "r"(st + boff[np] + ks * 32));
            #pragma unroll
            for (int mt = 0; mt < 4; mt++)
                #pragma unroll
                for (int np = 0; np < 2; np++)
                    #pragma unroll
                    for (int h = 0; h < 2; h++) {
                        float* d = acc[mt][np * 2 + h];
                        asm volatile(
                            "mma.sync.aligned.m16n8k16.row.col.f32.f16.f16.f32 "
                            "{%0,%1,%2,%3}, {%4,%5,%6,%7}, {%8,%9}, {%0,%1,%2,%3};\n"
                            : "+f"(d[0]), "+f"(d[1]), "+f"(d[2]), "+f"(d[3])
                            : "r"(a[mt][0]), "r"(a[mt][1]), "r"(a[mt][2]), "r"(a[mt][3]),
                              "r"(b[np][2 * h]), "r"(b[np][2 * h + 1]));
                    }
        }
        __syncthreads();
    }

    // epilogue
    const int r = lane >> 2, cc = lane & 3;
    #pragma unroll
    for (int mt = 0; mt < 4; mt++) {
        #pragma unroll
        for (int n8 = 0; n8 < 4; n8++) {
            size_t row = (size_t)bm * BM + wm + mt * 16 + r;
            size_t col = (size_t)bn * BN + wn + n8 * 8 + cc * 2;
            float* d = acc[mt][n8];
            *(float2*)(out + row * DOUT + col)       = make_float2(d[0], d[1]);
            *(float2*)(out + (row + 8) * DOUT + col) = make_float2(d[2], d[3]);
        }
    }
}

extern "C" void kernel_launch(void* const* d_in, const int* in_sizes, int n_in,
                              void* d_out, int out_size) {
    const float* x     = (const float*)d_in[0];
    const float* base  = (const float*)d_in[1];
    const int*   mask  = (const int*)d_in[2];
    const float* coeff = (const float*)d_in[3];
    float* out = (float*)d_out;

    pack_x<<<dim3(MTOT / 128, NKT), 256>>>(x);
    pack_w<<<dim3(DOUT / 128, NKT), 256>>>(base, mask, coeff);

    const int smem = STAGES * STAGEB;   // 81920
    cudaFuncSetAttribute(gemm_fp16, cudaFuncAttributeMaxDynamicSharedMemorySize, smem);
    gemm_fp16<<<(MTOT / BM) * (DOUT / BN), 256, smem>>>(out);
}

// round 5
// speedup vs baseline: 2.0234x; 1.3251x over previous
#include <cuda_runtime.h>
#include <cuda_fp16.h>
#include <cstdint>

#define DIN   4096
#define DOUT  4096
#define MTOT  8192
#define BM    128
#define BN    128
#define BK    32
#define NKT   (DIN / BK)      // 128
#define STAGES 4
#define ASTAGE 10240          // 128 rows * 5 chunks * 16B (padded)
#define STAGEB 20480          // A + B per stage

// Packed fp16 operand tiles. Tile (mb,kt) / (nb,kt) = 4096 halves contiguous,
// chunk c (16B, 8 halves) = row (c>>2), kchunk (c&3). A: [M][K]; B: [N][K] (W transposed).
__device__ __half g_A[(size_t)MTOT * DIN];
__device__ __half g_B[(size_t)DOUT * DIN];

__device__ __forceinline__ uint32_t smem_u32(const void* p) {
    uint32_t a;
    asm("{ .reg .u64 t; cvta.to.shared.u64 t, %1; cvt.u32.u64 %0, t; }" : "=r"(a) : "l"(p));
    return a;
}
__device__ __forceinline__ void cp16(uint32_t dst, const void* src) {
    asm volatile("cp.async.cg.shared.global [%0], [%1], 16;\n" :: "r"(dst), "l"(src));
}

// ---------- pack x -> fp16 tiles ----------
__global__ void __launch_bounds__(256) pack_x(const float* __restrict__ x) {
    int mb = blockIdx.x, kt = blockIdx.y;
    __half* tile = g_A + ((size_t)(mb * NKT + kt) << 12);
    #pragma unroll
    for (int it = 0; it < 2; it++) {
        int cid = it * 256 + threadIdx.x;            // 512 chunks of 8 halves
        int row = cid >> 2, kc = cid & 3;
        const float4* src = (const float4*)(x + (size_t)(mb * 128 + row) * DIN + kt * BK + kc * 8);
        float4 f0 = src[0], f1 = src[1];
        __half2 h0 = __floats2half2_rn(f0.x, f0.y);
        __half2 h1 = __floats2half2_rn(f0.z, f0.w);
        __half2 h2 = __floats2half2_rn(f1.x, f1.y);
        __half2 h3 = __floats2half2_rn(f1.z, f1.w);
        uint4 v;
        v.x = *(uint32_t*)&h0; v.y = *(uint32_t*)&h1;
        v.z = *(uint32_t*)&h2; v.w = *(uint32_t*)&h3;
        *(uint4*)(tile + cid * 8) = v;
    }
}

// ---------- fuse W = base + c*sign, transpose to [N][K] fp16 tiles ----------
__global__ void __launch_bounds__(256) pack_w(const float* __restrict__ base,
                                              const int* __restrict__ mask,
                                              const float* __restrict__ coeff) {
    __shared__ uint32_t sw32[128 * 17];              // [n][kpair], pad 17
    int nb = blockIdx.x, kt = blockIdx.y;
    int t = threadIdx.x;
    float c = __ldg(coeff);
    int n = t & 127, hsel = t >> 7;
    #pragma unroll
    for (int i = 0; i < 8; i++) {
        int kp = hsel * 8 + i;
        size_t off0 = (size_t)(kt * BK + kp * 2) * DOUT + nb * 128 + n;
        size_t off1 = off0 + DOUT;
        float w0 = base[off0] + (mask[off0] ? c : -c);
        float w1 = base[off1] + (mask[off1] ? c : -c);
        __half2 h = __floats2half2_rn(w0, w1);
        sw32[n * 17 + kp] = *(uint32_t*)&h;
    }
    __syncthreads();
    __half* tile = g_B + ((size_t)(nb * NKT + kt) << 12);
    #pragma unroll
    for (int it = 0; it < 2; it++) {
        int cid = it * 256 + t;
        int nn = cid >> 2, kc = cid & 3;
        uint4 v;
        v.x = sw32[nn * 17 + kc * 4 + 0];
        v.y = sw32[nn * 17 + kc * 4 + 1];
        v.z = sw32[nn * 17 + kc * 4 + 2];
        v.w = sw32[nn * 17 + kc * 4 + 3];
        *(uint4*)(tile + cid * 8) = v;
    }
}

// ---------- fp16 GEMM: out = A @ B^T, 4 warps, warp tile 64x64 ----------
__global__ void __launch_bounds__(128, 2) gemm_fp16(float* __restrict__ out) {
    extern __shared__ char smem[];
    const uint32_t sbase = smem_u32(smem);

    const int tid  = threadIdx.x;
    const int lane = tid & 31;
    const int warp = tid >> 5;                // 0..3
    const int wm = (warp & 1) * 64;           // warp tile 64(m) x 64(n)
    const int wn = (warp >> 1) * 64;

    // L2 block swizzle: 8 m-blocks share one n-block column
    int pid = blockIdx.x;
    int local = pid & 255, g = pid >> 8;
    int bm = (g << 3) + (local & 7);
    int bn = local >> 3;

    const __half* tA0 = g_A + ((size_t)bm * NKT << 12);
    const __half* tB0 = g_B + ((size_t)bn * NKT << 12);

    // ldmatrix per-lane base offsets (padded stride-5-chunk layout)
    const int j = lane >> 3, sub = lane & 7;
    uint32_t aoff[4], boff[4];
    #pragma unroll
    for (int mt = 0; mt < 4; mt++) {
        int m = wm + mt * 16 + (j & 1) * 8 + sub;
        aoff[mt] = (uint32_t)((m * 5 + (j >> 1)) << 4);
    }
    #pragma unroll
    for (int np = 0; np < 4; np++) {
        int n = wn + np * 16 + (j >> 1) * 8 + sub;
        boff[np] = (uint32_t)((n * 5 + (j & 1)) << 4) + ASTAGE;
    }

    float acc[4][8][4];
    #pragma unroll
    for (int a = 0; a < 4; a++)
        #pragma unroll
        for (int b = 0; b < 8; b++)
            #pragma unroll
            for (int d = 0; d < 4; d++) acc[a][b][d] = 0.f;

    auto issue = [&](int kt, int stage) {
        const __half* tA = tA0 + ((size_t)kt << 12);
        const __half* tB = tB0 + ((size_t)kt << 12);
        #pragma unroll
        for (int it = 0; it < 4; it++) {
            int cid = it * 128 + tid;             // 512 chunks each
            uint32_t d = sbase + stage * STAGEB + ((((cid >> 2) * 5) + (cid & 3)) << 4);
            cp16(d, tA + cid * 8);
            cp16(d + ASTAGE, tB + cid * 8);
        }
        asm volatile("cp.async.commit_group;\n");
    };

    issue(0, 0); issue(1, 1); issue(2, 2);

    #pragma unroll 1
    for (int kt = 0; kt < NKT; kt++) {
        if (kt + 3 < NKT) issue(kt + 3, (kt + 3) & 3);
        else asm volatile("cp.async.commit_group;\n");
        asm volatile("cp.async.wait_group 3;\n");
        __syncthreads();

        const uint32_t st = sbase + (kt & 3) * STAGEB;
        #pragma unroll
        for (int ks = 0; ks < 2; ks++) {
            uint32_t a[4][4], b[4][4];
            #pragma unroll
            for (int mt = 0; mt < 4; mt++)
                asm volatile("ldmatrix.sync.aligned.m8n8.x4.shared.b16 {%0,%1,%2,%3}, [%4];"
                             : "=r"(a[mt][0]), "=r"(a[mt][1]), "=r"(a[mt][2]), "=r"(a[mt][3])
                             : "r"(st + aoff[mt] + ks * 32));
            #pragma unroll
            for (int np = 0; np < 4; np++)
                asm volatile("ldmatrix.sync.aligned.m8n8.x4.shared.b16 {%0,%1,%2,%3}, [%4];"
                             : "=r"(b[np][0]), "=r"(b[np][1]), "=r"(b[np][2]), "=r"(b[np][3])
                             : "r"(st + boff[np] + ks * 32));
            #pragma unroll
            for (int mt = 0; mt < 4; mt++)
                #pragma unroll
                for (int np = 0; np < 4; np++)
                    #pragma unroll
                    for (int h = 0; h < 2; h++) {
                        float* d = acc[mt][np * 2 + h];
                        asm volatile(
                            "mma.sync.aligned.m16n8k16.row.col.f32.f16.f16.f32 "
                            "{%0,%1,%2,%3}, {%4,%5,%6,%7}, {%8,%9}, {%0,%1,%2,%3};\n"
                            : "+f"(d[0]), "+f"(d[1]), "+f"(d[2]), "+f"(d[3])
                            : "r"(a[mt][0]), "r"(a[mt][1]), "r"(a[mt][2]), "r"(a[mt][3]),
                              "r"(b[np][2 * h]), "r"(b[np][2 * h + 1]));
                    }
        }
        __syncthreads();
    }

    // epilogue
    const int r = lane >> 2, cc = lane & 3;
    #pragma unroll
    for (int mt = 0; mt < 4; mt++) {
        #pragma unroll
        for (int n8 = 0; n8 < 8; n8++) {
            size_t row = (size_t)bm * BM + wm + mt * 16 + r;
            size_t col = (size_t)bn * BN + wn + n8 * 8 + cc * 2;
            float* d = acc[mt][n8];
            *(float2*)(out + row * DOUT + col)       = make_float2(d[0], d[1]);
            *(float2*)(out + (row + 8) * DOUT + col) = make_float2(d[2], d[3]);
        }
    }
}

extern "C" void kernel_launch(void* const* d_in, const int* in_sizes, int n_in,
                              void* d_out, int out_size) {
    const float* x     = (const float*)d_in[0];
    const float* base  = (const float*)d_in[1];
    const int*   mask  = (const int*)d_in[2];
    const float* coeff = (const float*)d_in[3];
    float* out = (float*)d_out;

    pack_x<<<dim3(MTOT / 128, NKT), 256>>>(x);
    pack_w<<<dim3(DOUT / 128, NKT), 256>>>(base, mask, coeff);

    const int smem = STAGES * STAGEB;   // 81920
    cudaFuncSetAttribute(gemm_fp16, cudaFuncAttributeMaxDynamicSharedMemorySize, smem);
    gemm_fp16<<<(MTOT / BM) * (DOUT / BN), 128, smem>>>(out);
}